// round 13
// baseline (speedup 1.0000x reference)
#include <cuda_runtime.h>
#include <cuda_fp16.h>
#include <cstdint>
#include <math.h>

#define NB   64
#define HHH  56
#define WWW  56
#define EPS  1e-5f

// ---------------- global scratch (no cudaMalloc allowed) ----------------
#define NHWC_ELEMS (NB * HHH * WWW * 128)
__device__ __align__(16) __half g_xf[NHWC_ELEMS];
__device__ __align__(16) __half g_mf[NHWC_ELEMS];

// W fragment-major: [conv][ ((tap*8 + mtile)*8 + kg)*128 + lane*4 + r ], fp16 pairs.
#define WF_U32 (9 * 8 * 8 * 128)
__device__ __align__(16) uint32_t g_wf[2][WF_U32];

// ---------------- smem ----------------
// X slot: 60 rows (6 cols x 10 h) x 80B = 4800B. 2 slots (9600B).
// Epilogue region at 9600 (disjoint from X slots):
//   MODE0 eb [32 q][128 co] fp16 = 8192B ; MODE1 fs [128][33] fp32 = 16896B
#define X_SLOT     4800
#define EPI_OFF    9600
#define SMEM_BYTES (EPI_OFF + 16896)   // 26496

#define NTILES     (14 * 7 * NB)       // 6272
#define NPERS      740                 // 148 SMs x 5 CTAs

__device__ __forceinline__ uint32_t smem_u32(const void* p) {
    uint32_t a;
    asm("{ .reg .u64 t; cvta.to.shared.u64 t, %1; cvt.u32.u64 %0, t; }" : "=r"(a) : "l"(p));
    return a;
}
__device__ __forceinline__ void cp16(uint32_t dst, const void* src, uint32_t sz) {
    asm volatile("cp.async.cg.shared.global [%0], [%1], 16, %2;"
                 :: "r"(dst), "l"(src), "r"(sz));
}
#define CP_COMMIT() asm volatile("cp.async.commit_group;" ::: "memory")
#define CP_WAIT0()  asm volatile("cp.async.wait_group 0;" ::: "memory")

#define LDSM_X4(r, addr)                                                       \
    asm volatile("ldmatrix.sync.aligned.m8n8.x4.shared.b16 {%0,%1,%2,%3}, [%4];" \
        : "=r"((r)[0]), "=r"((r)[1]), "=r"((r)[2]), "=r"((r)[3]) : "r"(addr))

__device__ __forceinline__ void mma16816(float* d, const uint32_t* a, const uint32_t* b) {
    asm volatile(
        "mma.sync.aligned.m16n8k16.row.col.f32.f16.f16.f32 "
        "{%0,%1,%2,%3}, {%4,%5,%6,%7}, {%8,%9}, {%0,%1,%2,%3};"
        : "+f"(d[0]), "+f"(d[1]), "+f"(d[2]), "+f"(d[3])
        : "r"(a[0]), "r"(a[1]), "r"(a[2]), "r"(a[3]), "r"(b[0]), "r"(b[1]));
}

// ---- prep: NCHW fp32 x -> NHWC fp16 ----
__global__ void prep_x(const float* __restrict__ x) {
    __shared__ float s[128][57];
    const int n = blockIdx.y, h = blockIdx.x;
    for (int i = threadIdx.x; i < 128 * 56; i += blockDim.x) {
        int ci = i / 56, w = i - ci * 56;
        s[ci][w] = x[((long)(n * 128 + ci) * 56 + h) * 56 + w];
    }
    __syncthreads();
    for (int i = threadIdx.x; i < 128 * 56; i += blockDim.x) {
        int w = i >> 7, ci = i & 127;
        long idx = ((long)(n * 56 + h) * 56 + w) * 128 + ci;
        g_xf[idx] = __float2half(s[ci][w]);
    }
}

// ---- prep: OIHW fp32 w -> fragment-major fp16 ----
__global__ void prep_w(const float* __restrict__ w1, const float* __restrict__ w2) {
    int i = blockIdx.x * blockDim.x + threadIdx.x;
    if (i >= 2 * WF_U32) return;
    int conv = i / WF_U32;
    int r2   = i - conv * WF_U32;
    int tap  = r2 >> 13;
    int mt   = (r2 >> 10) & 7;
    int kg   = (r2 >> 7) & 7;
    int lane = (r2 >> 2) & 31;
    int r    = r2 & 3;
    int co = mt * 16 + (lane >> 2) + (r & 1) * 8;
    int ci = kg * 16 + (lane & 3) * 2 + (r >> 1) * 8;
    int kh = tap / 3, kw = tap - kh * 3;
    const float* w = conv ? w2 : w1;
    __half h0 = __float2half(w[((co * 128 + ci) * 3 + kh) * 3 + kw]);
    __half h1 = __float2half(w[((co * 128 + ci + 1) * 3 + kh) * 3 + kw]);
    g_wf[conv][r2] = (uint32_t)__half_as_ushort(h0) |
                     ((uint32_t)__half_as_ushort(h1) << 16);
}

// Persistent 128-thread CTAs (740 total), each loops tiles stride-740.
// Tile = 128co x 32q (4 cols x 8 rows). tile -> (n, band, cxt).
// MODE 0: src g_xf, w1, BN1, relu -> g_mf (NHWC fp16)
// MODE 1: src g_mf, w2, BN2, +x(NCHW), relu -> out (NCHW fp32)
template <int MODE>
__global__ void __launch_bounds__(128, 5)
conv_mma(const float* __restrict__ gamma, const float* __restrict__ beta,
         const float* __restrict__ mean,  const float* __restrict__ var,
         const float* __restrict__ resid, float* __restrict__ outp)
{
    extern __shared__ char smem[];
    const uint32_t sb = smem_u32(smem);
    const int tid  = threadIdx.x;
    const int lane = tid & 31;
    const int warpM = tid >> 5;          // 0..3

    const __half* src = (MODE == 0) ? g_xf : g_mf;
    const uint32_t* wf = &g_wf[MODE][(size_t)(warpM * 2) * 1024 + lane * 4];

    const int m0 = warpM * 32;
    const uint32_t b_off4 = (uint32_t)(lane & 7) * 80 + ((lane >> 3) & 3) * 16;

    // stage chunk of tile (n,h0,c0) into slot chunk&1
    auto stage_x = [&](int n, int h0, int c0, int chunk) {
        const int ci0 = chunk * 32;
        const uint32_t xb = sb + (uint32_t)(chunk & 1) * X_SLOT;
        for (int i = tid; i < 240; i += 128) {
            int row = i >> 2, seg = i & 3;
            int cx = row / 10, rh = row - cx * 10;
            int h = h0 + rh - 1, w = c0 + cx - 1;
            bool ok = ((unsigned)h < 56u) && ((unsigned)w < 56u);
            long gi = (((long)(n * 56 + (ok ? h : 0)) * 56 + (ok ? w : 0)) * 128
                       + ci0 + seg * 8);
            cp16(xb + row * 80 + seg * 16, src + gi, ok ? 16u : 0u);
        }
    };
    auto decomp = [](int tile, int& n, int& h0, int& c0) {
        n = tile / 98;
        int rem = tile - n * 98;
        int band = rem / 14;
        int cxt  = rem - band * 14;
        h0 = band * 8; c0 = cxt * 4;
    };

    int tile = blockIdx.x;
    int n, h0, c0;
    decomp(tile, n, h0, c0);
    stage_x(n, h0, c0, 0); CP_COMMIT();

#pragma unroll 1
    for (; tile < NTILES; tile += NPERS) {
        const int rot = tile % 3;
        const int ntile = tile + NPERS;

        float acc[2][4][4];
#pragma unroll
        for (int t = 0; t < 2; t++)
#pragma unroll
            for (int j = 0; j < 4; j++)
#pragma unroll
                for (int e = 0; e < 4; e++)
                    acc[t][j][e] = 0.0f;

#pragma unroll 1
        for (int chunk = 0; chunk < 4; chunk++) {
            CP_WAIT0();
            __syncthreads();
            if (chunk < 3) {
                stage_x(n, h0, c0, chunk + 1);
            } else if (ntile < NTILES) {
                int n2, h2, c2;
                decomp(ntile, n2, h2, c2);
                stage_x(n2, h2, c2, 0);      // slot 0 (free since chunk 2)
            }
            CP_COMMIT();

            const uint32_t xb = sb + (uint32_t)(chunk & 1) * X_SLOT;
#pragma unroll 1
            for (int kh0 = 0; kh0 < 3; kh0++) {
                int kh = kh0 + rot; if (kh >= 3) kh -= 3;
                // 6 shared B fragments cover all 3 kw taps of this kh
                uint32_t bq[6][4];
#pragma unroll
                for (int m = 0; m < 6; m++)
                    LDSM_X4(bq[m], xb + (uint32_t)(m * 10 + kh) * 80 + b_off4);

#pragma unroll
                for (int kw = 0; kw < 3; kw++) {
                    const int tap = kh * 3 + kw;
                    uint32_t a[2][2][4];   // [k16][mtile]
#pragma unroll
                    for (int k16 = 0; k16 < 2; k16++)
#pragma unroll
                        for (int mt = 0; mt < 2; mt++)
                            *reinterpret_cast<uint4*>(a[k16][mt]) =
                                *reinterpret_cast<const uint4*>(
                                    wf + tap * 8192 + mt * 1024 + (chunk * 2 + k16) * 128);
#pragma unroll
                    for (int j = 0; j < 4; j++) {
                        mma16816(acc[0][j], a[0][0], bq[kw + j]);
                        mma16816(acc[1][j], a[0][1], bq[kw + j]);
                        mma16816(acc[0][j], a[1][0], bq[kw + j] + 2);
                        mma16816(acc[1][j], a[1][1], bq[kw + j] + 2);
                    }
                }
            }
        }

        // ---------------- epilogue (region disjoint from X slots) ----------------
        float sc[2][2], bc[2][2];
#pragma unroll
        for (int t = 0; t < 2; t++)
#pragma unroll
            for (int hrow = 0; hrow < 2; hrow++) {
                int co = m0 + t * 16 + (lane >> 2) + hrow * 8;
                float s = gamma[co] * rsqrtf(var[co] + EPS);
                sc[t][hrow] = s;
                bc[t][hrow] = beta[co] - mean[co] * s;
            }

        if (MODE == 0) {
            __half* eb = reinterpret_cast<__half*>(smem + EPI_OFF);   // [32 q][128 co]
            __syncthreads();
#pragma unroll
            for (int t = 0; t < 2; t++)
#pragma unroll
                for (int j = 0; j < 4; j++)
#pragma unroll
                    for (int e = 0; e < 4; e++) {
                        int hrow = e >> 1;
                        int co = m0 + t * 16 + (lane >> 2) + hrow * 8;
                        int q  = j * 8 + (lane & 3) * 2 + (e & 1);
                        float v = fmaxf(fmaf(acc[t][j][e], sc[t][hrow], bc[t][hrow]), 0.0f);
                        eb[q * 128 + co] = __float2half(v);
                    }
            __syncthreads();
            for (int i = tid; i < 512; i += 128) {
                int q = i >> 4, seg = i & 15;
                uint4 v = reinterpret_cast<const uint4*>(eb)[i];
                *reinterpret_cast<uint4*>(g_mf +
                    ((long)((n * 56 + h0 + (q & 7)) * 56 + c0 + (q >> 3))) * 128 + seg * 8) = v;
            }
        } else {
            float* fs = reinterpret_cast<float*>(smem + EPI_OFF);   // [128 co][33]
            __syncthreads();
#pragma unroll
            for (int t = 0; t < 2; t++)
#pragma unroll
                for (int j = 0; j < 4; j++)
#pragma unroll
                    for (int e = 0; e < 4; e++) {
                        int hrow = e >> 1;
                        int co = m0 + t * 16 + (lane >> 2) + hrow * 8;
                        int r  = (lane & 3) * 2 + (e & 1);
                        fs[co * 33 + r * 4 + j] =
                            fmaf(acc[t][j][e], sc[t][hrow], bc[t][hrow]);
                    }
            __syncthreads();
            for (int i = tid; i < 128 * 32; i += 128) {
                int co  = i >> 5;
                int rem = i & 31;                // r*4 + c
                int r   = rem >> 2;
                int c   = rem & 3;
                long g = ((long)(n * 128 + co) * 56 + h0 + r) * 56 + c0 + c;
                float v = fs[co * 33 + rem] + resid[g];
                outp[g] = fmaxf(v, 0.0f);
            }
        }
        __syncthreads();   // protect epilogue smem before next tile

        if (ntile < NTILES) decomp(ntile, n, h0, c0);
    }
}

extern "C" void kernel_launch(void* const* d_in, const int* in_sizes, int n_in,
                              void* d_out, int out_size)
{
    const float* x      = (const float*)d_in[0];
    const float* w1     = (const float*)d_in[1];
    const float* w2     = (const float*)d_in[2];
    const float* gamma1 = (const float*)d_in[3];
    const float* beta1  = (const float*)d_in[4];
    const float* mean1  = (const float*)d_in[5];
    const float* var1   = (const float*)d_in[6];
    const float* gamma2 = (const float*)d_in[7];
    const float* beta2  = (const float*)d_in[8];
    const float* mean2  = (const float*)d_in[9];
    const float* var2   = (const float*)d_in[10];
    float* out = (float*)d_out;

    cudaFuncSetAttribute(conv_mma<0>, cudaFuncAttributeMaxDynamicSharedMemorySize, SMEM_BYTES);
    cudaFuncSetAttribute(conv_mma<1>, cudaFuncAttributeMaxDynamicSharedMemorySize, SMEM_BYTES);

    prep_x<<<dim3(HHH, NB), 256>>>(x);
    prep_w<<<(2 * WF_U32 + 255) / 256, 256>>>(w1, w2);

    conv_mma<0><<<NPERS, 128, SMEM_BYTES>>>(gamma1, beta1, mean1, var1, nullptr, nullptr);
    conv_mma<1><<<NPERS, 128, SMEM_BYTES>>>(gamma2, beta2, mean2, var2, x, out);
}

// round 14
// speedup vs baseline: 1.1117x; 1.1117x over previous
#include <cuda_runtime.h>
#include <cuda_fp16.h>
#include <cstdint>
#include <math.h>

#define NB   64
#define HHH  56
#define WWW  56
#define EPS  1e-5f

// ---------------- global scratch (no cudaMalloc allowed) ----------------
#define NHWC_ELEMS (NB * HHH * WWW * 128)
__device__ __align__(16) __half g_xf[NHWC_ELEMS];
__device__ __align__(16) __half g_mf[NHWC_ELEMS];

// W fragment-major: [conv][ ((tap*8 + mtile)*8 + kg)*128 + lane*4 + r ], fp16 pairs.
#define WF_U32 (9 * 8 * 8 * 128)
__device__ __align__(16) uint32_t g_wf[2][WF_U32];

// ---------------- smem ----------------
// X tile (full K): 60 rows (6 cols x 10 h) x 272B (256B data + 16B pad) = 16320B.
// Epilogue region at 16320: MODE0 eb [32][128] fp16 = 8192B; MODE1 fs [128][36] fp16 = 9216B.
#define X_STRIDE   272
#define EPI_OFF    16320
#define SMEM_BYTES (EPI_OFF + 9216)   // 25536

__device__ __forceinline__ uint32_t smem_u32(const void* p) {
    uint32_t a;
    asm("{ .reg .u64 t; cvta.to.shared.u64 t, %1; cvt.u32.u64 %0, t; }" : "=r"(a) : "l"(p));
    return a;
}
__device__ __forceinline__ void cp16(uint32_t dst, const void* src, uint32_t sz) {
    asm volatile("cp.async.cg.shared.global [%0], [%1], 16, %2;"
                 :: "r"(dst), "l"(src), "r"(sz));
}
#define CP_COMMIT() asm volatile("cp.async.commit_group;" ::: "memory")
#define CP_WAIT0()  asm volatile("cp.async.wait_group 0;" ::: "memory")

#define LDSM_X4(r, addr)                                                       \
    asm volatile("ldmatrix.sync.aligned.m8n8.x4.shared.b16 {%0,%1,%2,%3}, [%4];" \
        : "=r"((r)[0]), "=r"((r)[1]), "=r"((r)[2]), "=r"((r)[3]) : "r"(addr))

__device__ __forceinline__ void mma16816(float* d, const uint32_t* a, const uint32_t* b) {
    asm volatile(
        "mma.sync.aligned.m16n8k16.row.col.f32.f16.f16.f32 "
        "{%0,%1,%2,%3}, {%4,%5,%6,%7}, {%8,%9}, {%0,%1,%2,%3};"
        : "+f"(d[0]), "+f"(d[1]), "+f"(d[2]), "+f"(d[3])
        : "r"(a[0]), "r"(a[1]), "r"(a[2]), "r"(a[3]), "r"(b[0]), "r"(b[1]));
}

// ---- prep: NCHW fp32 x -> NHWC fp16 ----
__global__ void prep_x(const float* __restrict__ x) {
    __shared__ float s[128][57];
    const int n = blockIdx.y, h = blockIdx.x;
    for (int i = threadIdx.x; i < 128 * 56; i += blockDim.x) {
        int ci = i / 56, w = i - ci * 56;
        s[ci][w] = x[((long)(n * 128 + ci) * 56 + h) * 56 + w];
    }
    __syncthreads();
    for (int i = threadIdx.x; i < 128 * 56; i += blockDim.x) {
        int w = i >> 7, ci = i & 127;
        long idx = ((long)(n * 56 + h) * 56 + w) * 128 + ci;
        g_xf[idx] = __float2half(s[ci][w]);
    }
}

// ---- prep: OIHW fp32 w -> fragment-major fp16 ----
__global__ void prep_w(const float* __restrict__ w1, const float* __restrict__ w2) {
    int i = blockIdx.x * blockDim.x + threadIdx.x;
    if (i >= 2 * WF_U32) return;
    int conv = i / WF_U32;
    int r2   = i - conv * WF_U32;
    int tap  = r2 >> 13;
    int mt   = (r2 >> 10) & 7;
    int kg   = (r2 >> 7) & 7;
    int lane = (r2 >> 2) & 31;
    int r    = r2 & 3;
    int co = mt * 16 + (lane >> 2) + (r & 1) * 8;
    int ci = kg * 16 + (lane & 3) * 2 + (r >> 1) * 8;
    int kh = tap / 3, kw = tap - kh * 3;
    const float* w = conv ? w2 : w1;
    __half h0 = __float2half(w[((co * 128 + ci) * 3 + kh) * 3 + kw]);
    __half h1 = __float2half(w[((co * 128 + ci + 1) * 3 + kh) * 3 + kw]);
    g_wf[conv][r2] = (uint32_t)__half_as_ushort(h0) |
                     ((uint32_t)__half_as_ushort(h1) << 16);
}

// 128-thread CTA, 4 warps = 4 warpM tiles; CTA tile = 128co x 32q (4 cols x 8 rows).
// Whole K=128 staged once -> barrier-free mainloop (2 syncthreads per CTA total).
// MODE 0: src g_xf, w1, BN1, relu -> g_mf (NHWC fp16)
// MODE 1: src g_mf, w2, BN2, +x(NCHW), relu -> out (NCHW fp32)
template <int MODE>
__global__ void __launch_bounds__(128, 5)
conv_mma(const float* __restrict__ gamma, const float* __restrict__ beta,
         const float* __restrict__ mean,  const float* __restrict__ var,
         const float* __restrict__ resid, float* __restrict__ outp)
{
    extern __shared__ char smem[];
    const uint32_t sb = smem_u32(smem);
    const int tid  = threadIdx.x;
    const int lane = tid & 31;
    const int warpM = tid >> 5;          // 0..3
    const int n  = blockIdx.z;
    const int h0 = blockIdx.y * 8;
    const int c0 = blockIdx.x * 4;

    const __half* src = (MODE == 0) ? g_xf : g_mf;
    const uint32_t* wf = &g_wf[MODE][(size_t)(warpM * 2) * 1024 + lane * 4];

    // ---- stage entire X tile (60 rows x 256B), one commit ----
    for (int i = tid; i < 960; i += 128) {
        int row = i >> 4, seg = i & 15;
        int cx = row / 10, rh = row - cx * 10;
        int h = h0 + rh - 1, w = c0 + cx - 1;
        bool ok = ((unsigned)h < 56u) && ((unsigned)w < 56u);
        long gi = (((long)(n * 56 + (ok ? h : 0)) * 56 + (ok ? w : 0)) * 128 + seg * 8);
        cp16(sb + row * X_STRIDE + seg * 16, src + gi, ok ? 16u : 0u);
    }
    CP_COMMIT();

    float acc[2][4][4];
#pragma unroll
    for (int t = 0; t < 2; t++)
#pragma unroll
        for (int j = 0; j < 4; j++)
#pragma unroll
            for (int e = 0; e < 4; e++)
                acc[t][j][e] = 0.0f;

    const int m0 = warpM * 32;
    const uint32_t b_off4 = (uint32_t)(lane & 7) * X_STRIDE + ((lane >> 3) & 3) * 16;

    CP_WAIT0();
    __syncthreads();      // sync #1: X tile visible to all warps

    // ---- barrier-free mainloop over full K ----
#pragma unroll 1
    for (int kc = 0; kc < 4; kc++) {
#pragma unroll 1
        for (int kh = 0; kh < 3; kh++) {
            // 6 shared B fragments cover all 3 kw taps of this kh
            uint32_t bq[6][4];
#pragma unroll
            for (int m = 0; m < 6; m++)
                LDSM_X4(bq[m],
                    sb + (uint32_t)(m * 10 + kh) * X_STRIDE + kc * 64 + b_off4);

#pragma unroll
            for (int kw = 0; kw < 3; kw++) {
                const int tap = kh * 3 + kw;
                uint32_t a[2][2][4];   // [k16][mtile]
#pragma unroll
                for (int k16 = 0; k16 < 2; k16++)
#pragma unroll
                    for (int mt = 0; mt < 2; mt++)
                        *reinterpret_cast<uint4*>(a[k16][mt]) =
                            *reinterpret_cast<const uint4*>(
                                wf + tap * 8192 + mt * 1024 + (kc * 2 + k16) * 128);
#pragma unroll
                for (int j = 0; j < 4; j++) {
                    mma16816(acc[0][j], a[0][0], bq[kw + j]);
                    mma16816(acc[1][j], a[0][1], bq[kw + j]);
                    mma16816(acc[0][j], a[1][0], bq[kw + j] + 2);
                    mma16816(acc[1][j], a[1][1], bq[kw + j] + 2);
                }
            }
        }
    }

    // ---------------- epilogue ----------------
    float sc[2][2], bc[2][2];
#pragma unroll
    for (int t = 0; t < 2; t++)
#pragma unroll
        for (int hrow = 0; hrow < 2; hrow++) {
            int co = m0 + t * 16 + (lane >> 2) + hrow * 8;
            float s = gamma[co] * rsqrtf(var[co] + EPS);
            sc[t][hrow] = s;
            bc[t][hrow] = beta[co] - mean[co] * s;
        }

    if (MODE == 0) {
        __half* eb = reinterpret_cast<__half*>(smem + EPI_OFF);   // [32 q][128 co]
#pragma unroll
        for (int t = 0; t < 2; t++)
#pragma unroll
            for (int j = 0; j < 4; j++)
#pragma unroll
                for (int e = 0; e < 4; e++) {
                    int hrow = e >> 1;
                    int co = m0 + t * 16 + (lane >> 2) + hrow * 8;
                    int q  = j * 8 + (lane & 3) * 2 + (e & 1);
                    float v = fmaxf(fmaf(acc[t][j][e], sc[t][hrow], bc[t][hrow]), 0.0f);
                    eb[q * 128 + co] = __float2half(v);
                }
        __syncthreads();  // sync #2
        for (int i = tid; i < 512; i += 128) {
            int q = i >> 4, seg = i & 15;
            uint4 v = reinterpret_cast<const uint4*>(eb)[i];
            *reinterpret_cast<uint4*>(g_mf +
                ((long)((n * 56 + h0 + (q & 7)) * 56 + c0 + (q >> 3))) * 128 + seg * 8) = v;
        }
    } else {
        __half* fs = reinterpret_cast<__half*>(smem + EPI_OFF);   // [128 co][36]
#pragma unroll
        for (int t = 0; t < 2; t++)
#pragma unroll
            for (int j = 0; j < 4; j++)
#pragma unroll
                for (int e = 0; e < 4; e++) {
                    int hrow = e >> 1;
                    int co = m0 + t * 16 + (lane >> 2) + hrow * 8;
                    int r  = (lane & 3) * 2 + (e & 1);
                    fs[co * 36 + r * 4 + j] = __float2half(
                        fmaf(acc[t][j][e], sc[t][hrow], bc[t][hrow]));
                }
        __syncthreads();  // sync #2
        for (int i = tid; i < 128 * 32; i += 128) {
            int co  = i >> 5;
            int rem = i & 31;                // r*4 + c
            int r   = rem >> 2;
            int c   = rem & 3;
            long g = ((long)(n * 128 + co) * 56 + h0 + r) * 56 + c0 + c;
            float v = __half2float(fs[co * 36 + rem]) + resid[g];
            outp[g] = fmaxf(v, 0.0f);
        }
    }
}

extern "C" void kernel_launch(void* const* d_in, const int* in_sizes, int n_in,
                              void* d_out, int out_size)
{
    const float* x      = (const float*)d_in[0];
    const float* w1     = (const float*)d_in[1];
    const float* w2     = (const float*)d_in[2];
    const float* gamma1 = (const float*)d_in[3];
    const float* beta1  = (const float*)d_in[4];
    const float* mean1  = (const float*)d_in[5];
    const float* var1   = (const float*)d_in[6];
    const float* gamma2 = (const float*)d_in[7];
    const float* beta2  = (const float*)d_in[8];
    const float* mean2  = (const float*)d_in[9];
    const float* var2   = (const float*)d_in[10];
    float* out = (float*)d_out;

    cudaFuncSetAttribute(conv_mma<0>, cudaFuncAttributeMaxDynamicSharedMemorySize, SMEM_BYTES);
    cudaFuncSetAttribute(conv_mma<1>, cudaFuncAttributeMaxDynamicSharedMemorySize, SMEM_BYTES);

    prep_x<<<dim3(HHH, NB), 256>>>(x);
    prep_w<<<(2 * WF_U32 + 255) / 256, 256>>>(w1, w2);

    dim3 grid(14, 7, NB);   // 14 col-tiles x 7 row-bands x 64 images
    conv_mma<0><<<grid, 128, SMEM_BYTES>>>(gamma1, beta1, mean1, var1, nullptr, nullptr);
    conv_mma<1><<<grid, 128, SMEM_BYTES>>>(gamma2, beta2, mean2, var2, x, out);
}